// round 1
// baseline (speedup 1.0000x reference)
#include <cuda_runtime.h>
#include <cuda_bf16.h>
#include <math.h>

// ---------------------------------------------------------------------------
// GNNRegressor: 2x GCNConv(+relu) -> global_mean_pool -> Linear+relu -> Linear+sigmoid
// N=50000 nodes, E=1.6M edges, IN=384, HID=128, G=512, OUT=5
// ---------------------------------------------------------------------------

#define N_NODES 50000
#define N_GRAPHS 512
#define HID 128
#define IN_DIM 384

// Scratch (device globals; no allocation allowed)
__device__ float g_H[(size_t)N_NODES * HID];    // gemm output / layer input
__device__ float g_B[(size_t)N_NODES * HID];    // second gemm output
__device__ float g_acc[(size_t)N_NODES * HID];  // scatter accumulator
__device__ float g_dis[N_NODES];                // deg -> rsqrt(deg)
__device__ float g_pool[(size_t)N_GRAPHS * HID];
__device__ float g_cnt[N_GRAPHS];

__device__ __forceinline__ void red_add_v4(float* addr, float4 v) {
    asm volatile("red.global.add.v4.f32 [%0], {%1,%2,%3,%4};"
                 :: "l"(addr), "f"(v.x), "f"(v.y), "f"(v.z), "f"(v.w)
                 : "memory");
}

// ---- degree ----------------------------------------------------------------
__global__ void k_init_deg(int n) {
    int i = blockIdx.x * blockDim.x + threadIdx.x;
    if (i < n) g_dis[i] = 1.0f;  // self loop
}

__global__ void k_edge_deg(const int* __restrict__ dst, int E) {
    int e = blockIdx.x * blockDim.x + threadIdx.x;
    if (e < E) atomicAdd(&g_dis[dst[e]], 1.0f);
}

__global__ void k_rsqrt_deg(int n) {
    int i = blockIdx.x * blockDim.x + threadIdx.x;
    if (i < n) g_dis[i] = rsqrtf(g_dis[i]);
}

// ---- GEMM: C[M,128] = A[M,K] @ W[K,128] ------------------------------------
template <int KTOT>
__global__ void k_gemm(const float* __restrict__ A, const float* __restrict__ W,
                       float* __restrict__ C, int M) {
    constexpr int BK = 8, BM = 64, BN = 128;
    __shared__ float As[BK][BM];
    __shared__ float Bs[BK][BN];
    const int t = threadIdx.x;               // 256 threads
    const int rg = t >> 5;                   // 0..7 (row group)
    const int cg = t & 31;                   // 0..31 (col group)
    const int row0 = blockIdx.x * BM;

    float acc[8][4] = {};

    for (int k0 = 0; k0 < KTOT; k0 += BK) {
        // load A tile: 64x8 = 512 elems, 2 per thread
        #pragma unroll
        for (int i = 0; i < 2; i++) {
            int idx = t * 2 + i;
            int r = idx >> 3, c = idx & 7;
            int row = row0 + r;
            As[c][r] = (row < M) ? A[(size_t)row * KTOT + k0 + c] : 0.0f;
        }
        // load W tile: 8x128, float4 per thread
        {
            int r = t >> 5;
            int c = (t & 31) * 4;
            float4 bv = *(const float4*)&W[(size_t)(k0 + r) * BN + c];
            *(float4*)&Bs[r][c] = bv;
        }
        __syncthreads();

        #pragma unroll
        for (int kk = 0; kk < BK; kk++) {
            float a[8];
            #pragma unroll
            for (int i = 0; i < 8; i++) a[i] = As[kk][rg * 8 + i];
            float4 bv = *(float4*)&Bs[kk][cg * 4];
            float b[4] = {bv.x, bv.y, bv.z, bv.w};
            #pragma unroll
            for (int i = 0; i < 8; i++)
                #pragma unroll
                for (int j = 0; j < 4; j++)
                    acc[i][j] += a[i] * b[j];
        }
        __syncthreads();
    }

    #pragma unroll
    for (int i = 0; i < 8; i++) {
        int row = row0 + rg * 8 + i;
        if (row < M) {
            float4 v = {acc[i][0], acc[i][1], acc[i][2], acc[i][3]};
            *(float4*)&C[(size_t)row * 128 + cg * 4] = v;
        }
    }
}

// ---- propagate -------------------------------------------------------------
// acc[i] = H[i] * dis[i]^2   (self loop term)
__global__ void k_self_init(const float* __restrict__ H, int n) {
    int idx = blockIdx.x * blockDim.x + threadIdx.x;
    int node = idx >> 5, chunk = idx & 31;
    if (node >= n) return;
    float s = g_dis[node];
    s = s * s;
    float4 h = ((const float4*)(H + (size_t)node * 128))[chunk];
    h.x *= s; h.y *= s; h.z *= s; h.w *= s;
    ((float4*)(g_acc + (size_t)node * 128))[chunk] = h;
}

// acc[dst] += H[src] * dis[src]*dis[dst]   (one warp per edge)
__global__ void k_scatter(const float* __restrict__ H, const int* __restrict__ src,
                          const int* __restrict__ dst, int E) {
    int gw = (blockIdx.x * blockDim.x + threadIdx.x) >> 5;
    int lane = threadIdx.x & 31;
    if (gw >= E) return;
    int s = __ldg(&src[gw]);
    int d = __ldg(&dst[gw]);
    float nrm = g_dis[s] * g_dis[d];
    float4 h = ((const float4*)(H + (size_t)s * 128))[lane];
    h.x *= nrm; h.y *= nrm; h.z *= nrm; h.w *= nrm;
    red_add_v4((float*)&((float4*)(g_acc + (size_t)d * 128))[lane], h);
}

// out = relu(acc + bias)
__global__ void k_finish(const float* __restrict__ bias, float* __restrict__ out, int n) {
    int idx = blockIdx.x * blockDim.x + threadIdx.x;  // float4 index
    if (idx >= n * 32) return;
    int c = (idx & 31) * 4;
    float4 a = ((const float4*)g_acc)[idx];
    float4 b = *(const float4*)&bias[c];
    a.x = fmaxf(a.x + b.x, 0.f);
    a.y = fmaxf(a.y + b.y, 0.f);
    a.z = fmaxf(a.z + b.z, 0.f);
    a.w = fmaxf(a.w + b.w, 0.f);
    ((float4*)out)[idx] = a;
}

// ---- pooling ---------------------------------------------------------------
__global__ void k_pool_zero() {
    int i = blockIdx.x * blockDim.x + threadIdx.x;
    if (i < N_GRAPHS * HID) g_pool[i] = 0.0f;
    if (i < N_GRAPHS) g_cnt[i] = 0.0f;
}

__global__ void k_pool(const float* __restrict__ H, const int* __restrict__ batch, int n) {
    int idx = blockIdx.x * blockDim.x + threadIdx.x;
    int node = idx >> 5, chunk = idx & 31;
    if (node >= n) return;
    int b = __ldg(&batch[node]);
    float4 h = ((const float4*)(H + (size_t)node * 128))[chunk];
    red_add_v4(&g_pool[(size_t)b * 128 + chunk * 4], h);
    if (chunk == 0) atomicAdd(&g_cnt[b], 1.0f);
}

// ---- MLP head: [512,128] -> relu(@Wl1[128,64]+bl1) -> sigmoid(@Wl2[64,5]+bl2)
__global__ void k_mlp(const float* __restrict__ Wl1, const float* __restrict__ bl1,
                      const float* __restrict__ Wl2, const float* __restrict__ bl2,
                      float* __restrict__ out) {
    __shared__ float gm[128];
    __shared__ float hid[64];
    int gi = blockIdx.x;
    int t = threadIdx.x;  // 64 threads
    float inv = 1.0f / fmaxf(g_cnt[gi], 1.0f);
    gm[t]      = g_pool[(size_t)gi * 128 + t] * inv;
    gm[t + 64] = g_pool[(size_t)gi * 128 + t + 64] * inv;
    __syncthreads();
    float s = bl1[t];
    #pragma unroll 8
    for (int k = 0; k < 128; k++) s += gm[k] * Wl1[k * 64 + t];
    hid[t] = fmaxf(s, 0.0f);
    __syncthreads();
    if (t < 5) {
        float o = bl2[t];
        #pragma unroll
        for (int k = 0; k < 64; k++) o += hid[k] * Wl2[k * 5 + t];
        out[gi * 5 + t] = 1.0f / (1.0f + expf(-o));
    }
}

// ---------------------------------------------------------------------------
extern "C" void kernel_launch(void* const* d_in, const int* in_sizes, int n_in,
                              void* d_out, int out_size) {
    const float* x    = (const float*)d_in[0];
    const int*   ei   = (const int*)d_in[1];   // [2, E] int32
    const int*   batch= (const int*)d_in[2];
    const float* W1   = (const float*)d_in[3];
    const float* b1   = (const float*)d_in[4];
    const float* W2   = (const float*)d_in[5];
    const float* b2   = (const float*)d_in[6];
    const float* Wl1  = (const float*)d_in[7];
    const float* bl1  = (const float*)d_in[8];
    const float* Wl2  = (const float*)d_in[9];
    const float* bl2  = (const float*)d_in[10];
    float* out = (float*)d_out;

    const int N = in_sizes[2];          // 50000
    const int E = in_sizes[1] / 2;      // 1600000
    const int* src = ei;
    const int* dst = ei + E;

    float* H = nullptr; float* B = nullptr;
    cudaGetSymbolAddress((void**)&H, g_H);
    cudaGetSymbolAddress((void**)&B, g_B);

    const int T = 256;

    // degrees -> dis
    k_init_deg<<<(N + T - 1) / T, T>>>(N);
    k_edge_deg<<<(E + T - 1) / T, T>>>(dst, E);
    k_rsqrt_deg<<<(N + T - 1) / T, T>>>(N);

    // layer 1
    k_gemm<IN_DIM><<<(N + 63) / 64, 256>>>(x, W1, H, N);
    k_self_init<<<(N * 32 + T - 1) / T, T>>>(H, N);
    k_scatter<<<(E * 32 + T - 1) / T, T>>>(H, src, dst, E);
    k_finish<<<(N * 32 + T - 1) / T, T>>>(b1, H, N);   // relu(acc+b1) -> H

    // layer 2
    k_gemm<HID><<<(N + 63) / 64, 256>>>(H, W2, B, N);
    k_self_init<<<(N * 32 + T - 1) / T, T>>>(B, N);
    k_scatter<<<(E * 32 + T - 1) / T, T>>>(B, src, dst, E);
    k_finish<<<(N * 32 + T - 1) / T, T>>>(b2, B, N);   // relu(acc+b2) -> B

    // pooling + head
    k_pool_zero<<<(N_GRAPHS * HID + T - 1) / T, T>>>();
    k_pool<<<(N * 32 + T - 1) / T, T>>>(B, batch, N);
    k_mlp<<<N_GRAPHS, 64>>>(Wl1, bl1, Wl2, bl2, out);
}

// round 2
// speedup vs baseline: 1.6449x; 1.6449x over previous
#include <cuda_runtime.h>
#include <cuda_bf16.h>
#include <math.h>

// ---------------------------------------------------------------------------
// GNNRegressor: 2x GCNConv(+relu) -> global_mean_pool -> Linear+relu -> Linear+sigmoid
// N=50000 nodes, E=1.6M edges, IN=384, HID=128, G=512, OUT=5
// Strategy: per-call CSR build (by dst), register-accumulating aggregate
// (1 warp/node), 128x128 SIMT fp32 GEMM.
// ---------------------------------------------------------------------------

#define N_NODES 50000
#define N_GRAPHS 512
#define HID 128
#define IN_DIM 384
#define E_MAX 1600000

// Scratch (device globals; no allocation allowed)
__device__ float g_H[(size_t)N_NODES * HID];     // gemm output (pre-aggregate)
__device__ float g_B[(size_t)N_NODES * HID];     // aggregate output (post-relu)
__device__ float g_dis[N_NODES];                 // rsqrt(deg+1)
__device__ int   g_deg[N_NODES];
__device__ int   g_row[N_NODES + 1];
__device__ int   g_cursor[N_NODES];
__device__ int   g_csr[E_MAX];
__device__ int   g_partials[256];
__device__ float g_pool[(size_t)N_GRAPHS * HID];
__device__ float g_cnt[N_GRAPHS];

__device__ __forceinline__ void red_add_v4(float* addr, float4 v) {
    asm volatile("red.global.add.v4.f32 [%0], {%1,%2,%3,%4};"
                 :: "l"(addr), "f"(v.x), "f"(v.y), "f"(v.z), "f"(v.w)
                 : "memory");
}

// ---- degree + CSR build -----------------------------------------------------
__global__ void k_zero_deg(int n) {
    int i = blockIdx.x * blockDim.x + threadIdx.x;
    if (i < n) g_deg[i] = 0;
}

__global__ void k_edge_count(const int* __restrict__ dst, int E) {
    int e = blockIdx.x * blockDim.x + threadIdx.x;
    if (e < E) atomicAdd(&g_deg[dst[e]], 1);
}

__global__ void k_dis(int n) {
    int i = blockIdx.x * blockDim.x + threadIdx.x;
    if (i < n) g_dis[i] = rsqrtf((float)(g_deg[i] + 1));
}

// block sums over 256-elem chunks of deg (covers n+1 with deg[n]=0 virtual)
__global__ void k_block_sums(int n) {
    __shared__ int sh[256];
    int i = blockIdx.x * 256 + threadIdx.x;
    int v = (i < n) ? g_deg[i] : 0;
    sh[threadIdx.x] = v;
    __syncthreads();
    #pragma unroll
    for (int off = 128; off > 0; off >>= 1) {
        if (threadIdx.x < off) sh[threadIdx.x] += sh[threadIdx.x + off];
        __syncthreads();
    }
    if (threadIdx.x == 0) g_partials[blockIdx.x] = sh[0];
}

// exclusive scan of partials (<=256) in one block
__global__ void k_scan_partials(int nb) {
    __shared__ int sh[256];
    int t = threadIdx.x;
    int v = (t < nb) ? g_partials[t] : 0;
    sh[t] = v;
    __syncthreads();
    #pragma unroll
    for (int off = 1; off < 256; off <<= 1) {
        int x = (t >= off) ? sh[t - off] : 0;
        __syncthreads();
        sh[t] += x;
        __syncthreads();
    }
    if (t < nb) g_partials[t] = sh[t] - v;  // exclusive
}

// final scan: row_start[i] = exclusive prefix of deg; also copy to cursor
__global__ void k_scan_final(int n) {
    __shared__ int sh[256];
    int i = blockIdx.x * 256 + threadIdx.x;
    int t = threadIdx.x;
    int v = (i < n) ? g_deg[i] : 0;
    sh[t] = v;
    __syncthreads();
    #pragma unroll
    for (int off = 1; off < 256; off <<= 1) {
        int x = (t >= off) ? sh[t - off] : 0;
        __syncthreads();
        sh[t] += x;
        __syncthreads();
    }
    int excl = sh[t] - v + g_partials[blockIdx.x];
    if (i <= n) {
        g_row[i] = excl;
        if (i < n) g_cursor[i] = excl;
    }
}

__global__ void k_fill_csr(const int* __restrict__ src, const int* __restrict__ dst, int E) {
    int e = blockIdx.x * blockDim.x + threadIdx.x;
    if (e < E) {
        int d = dst[e];
        int pos = atomicAdd(&g_cursor[d], 1);
        g_csr[pos] = src[e];
    }
}

// ---- GEMM: C[M,128] = A[M,K] @ W[K,128], fp32 SIMT, 128x128 tile -----------
template <int KTOT>
__global__ __launch_bounds__(256, 2)
void k_gemm(const float* __restrict__ A, const float* __restrict__ W,
            float* __restrict__ C, int M) {
    constexpr int BM = 128, BN = 128, BK = 8;
    __shared__ float As[BK][BM];
    __shared__ float Bs[BK][BN];
    const int t = threadIdx.x;                 // 256 threads
    const int rg = t >> 4;                     // 0..15
    const int cg = t & 15;                     // 0..15
    const int row0 = blockIdx.x * BM;

    const int arow = t >> 1;                   // 0..127
    const int acol = (t & 1) * 4;              // 0 or 4
    const int brow = t >> 5;                   // 0..7
    const int bcol = (t & 31) * 4;             // 0..124

    float acc00[4][4] = {}, acc01[4][4] = {}, acc10[4][4] = {}, acc11[4][4] = {};

    for (int k0 = 0; k0 < KTOT; k0 += BK) {
        int grow = row0 + arow;
        float4 av = (grow < M) ? *(const float4*)&A[(size_t)grow * KTOT + k0 + acol]
                               : make_float4(0.f, 0.f, 0.f, 0.f);
        As[acol + 0][arow] = av.x;
        As[acol + 1][arow] = av.y;
        As[acol + 2][arow] = av.z;
        As[acol + 3][arow] = av.w;
        *(float4*)&Bs[brow][bcol] = *(const float4*)&W[(size_t)(k0 + brow) * BN + bcol];
        __syncthreads();

        #pragma unroll
        for (int kk = 0; kk < BK; kk++) {
            float4 a0 = *(float4*)&As[kk][rg * 4];
            float4 a1 = *(float4*)&As[kk][rg * 4 + 64];
            float4 b0 = *(float4*)&Bs[kk][cg * 4];
            float4 b1 = *(float4*)&Bs[kk][cg * 4 + 64];
            float a0v[4] = {a0.x, a0.y, a0.z, a0.w};
            float a1v[4] = {a1.x, a1.y, a1.z, a1.w};
            float b0v[4] = {b0.x, b0.y, b0.z, b0.w};
            float b1v[4] = {b1.x, b1.y, b1.z, b1.w};
            #pragma unroll
            for (int i = 0; i < 4; i++)
                #pragma unroll
                for (int j = 0; j < 4; j++) {
                    acc00[i][j] += a0v[i] * b0v[j];
                    acc01[i][j] += a0v[i] * b1v[j];
                    acc10[i][j] += a1v[i] * b0v[j];
                    acc11[i][j] += a1v[i] * b1v[j];
                }
        }
        __syncthreads();
    }

    #pragma unroll
    for (int i = 0; i < 4; i++) {
        int r0 = row0 + rg * 4 + i;
        int r1 = r0 + 64;
        if (r0 < M) {
            *(float4*)&C[(size_t)r0 * 128 + cg * 4]      = *(float4*)&acc00[i][0];
            *(float4*)&C[(size_t)r0 * 128 + cg * 4 + 64] = *(float4*)&acc01[i][0];
        }
        if (r1 < M) {
            *(float4*)&C[(size_t)r1 * 128 + cg * 4]      = *(float4*)&acc10[i][0];
            *(float4*)&C[(size_t)r1 * 128 + cg * 4 + 64] = *(float4*)&acc11[i][0];
        }
    }
}

// ---- aggregate: out[d] = relu(dis_d*(Sum_{s in row d} dis_s*h[s] + dis_d*h[d]) + bias)
__global__ void k_aggregate(const float* __restrict__ H, const float* __restrict__ bias,
                            float* __restrict__ out, int n) {
    int warp = (blockIdx.x * blockDim.x + threadIdx.x) >> 5;
    int lane = threadIdx.x & 31;
    if (warp >= n) return;
    const int node = warp;
    const float4* __restrict__ H4 = (const float4*)H;

    int beg = g_row[node];
    int end = g_row[node + 1];

    float4 a0 = {0, 0, 0, 0}, a1 = {0, 0, 0, 0}, a2 = {0, 0, 0, 0}, a3 = {0, 0, 0, 0};

    int j = beg;
    for (; j + 3 < end; j += 4) {
        int s0 = __ldg(&g_csr[j + 0]);
        int s1 = __ldg(&g_csr[j + 1]);
        int s2 = __ldg(&g_csr[j + 2]);
        int s3 = __ldg(&g_csr[j + 3]);
        float w0 = __ldg(&g_dis[s0]);
        float w1 = __ldg(&g_dis[s1]);
        float w2 = __ldg(&g_dis[s2]);
        float w3 = __ldg(&g_dis[s3]);
        float4 h0 = __ldg(&H4[(size_t)s0 * 32 + lane]);
        float4 h1 = __ldg(&H4[(size_t)s1 * 32 + lane]);
        float4 h2 = __ldg(&H4[(size_t)s2 * 32 + lane]);
        float4 h3 = __ldg(&H4[(size_t)s3 * 32 + lane]);
        a0.x += w0 * h0.x; a0.y += w0 * h0.y; a0.z += w0 * h0.z; a0.w += w0 * h0.w;
        a1.x += w1 * h1.x; a1.y += w1 * h1.y; a1.z += w1 * h1.z; a1.w += w1 * h1.w;
        a2.x += w2 * h2.x; a2.y += w2 * h2.y; a2.z += w2 * h2.z; a2.w += w2 * h2.w;
        a3.x += w3 * h3.x; a3.y += w3 * h3.y; a3.z += w3 * h3.z; a3.w += w3 * h3.w;
    }
    for (; j < end; j++) {
        int s = __ldg(&g_csr[j]);
        float w = __ldg(&g_dis[s]);
        float4 h = __ldg(&H4[(size_t)s * 32 + lane]);
        a0.x += w * h.x; a0.y += w * h.y; a0.z += w * h.z; a0.w += w * h.w;
    }

    float dd = g_dis[node];
    float4 hs = __ldg(&H4[(size_t)node * 32 + lane]);
    float4 acc;
    acc.x = dd * ((a0.x + a1.x) + (a2.x + a3.x) + dd * hs.x);
    acc.y = dd * ((a0.y + a1.y) + (a2.y + a3.y) + dd * hs.y);
    acc.z = dd * ((a0.z + a1.z) + (a2.z + a3.z) + dd * hs.z);
    acc.w = dd * ((a0.w + a1.w) + (a2.w + a3.w) + dd * hs.w);

    float4 b = *(const float4*)&bias[lane * 4];
    acc.x = fmaxf(acc.x + b.x, 0.f);
    acc.y = fmaxf(acc.y + b.y, 0.f);
    acc.z = fmaxf(acc.z + b.z, 0.f);
    acc.w = fmaxf(acc.w + b.w, 0.f);
    ((float4*)out)[(size_t)node * 32 + lane] = acc;
}

// ---- pooling ---------------------------------------------------------------
__global__ void k_pool_zero() {
    int i = blockIdx.x * blockDim.x + threadIdx.x;
    if (i < N_GRAPHS * HID) g_pool[i] = 0.0f;
    if (i < N_GRAPHS) g_cnt[i] = 0.0f;
}

__global__ void k_pool(const float* __restrict__ H, const int* __restrict__ batch, int n) {
    int idx = blockIdx.x * blockDim.x + threadIdx.x;
    int node = idx >> 5, chunk = idx & 31;
    if (node >= n) return;
    int b = __ldg(&batch[node]);
    float4 h = ((const float4*)(H + (size_t)node * 128))[chunk];
    red_add_v4(&g_pool[(size_t)b * 128 + chunk * 4], h);
    if (chunk == 0) atomicAdd(&g_cnt[b], 1.0f);
}

// ---- MLP head: [512,128] -> relu(@Wl1[128,64]+bl1) -> sigmoid(@Wl2[64,5]+bl2)
__global__ void k_mlp(const float* __restrict__ Wl1, const float* __restrict__ bl1,
                      const float* __restrict__ Wl2, const float* __restrict__ bl2,
                      float* __restrict__ out) {
    __shared__ float gm[128];
    __shared__ float hid[64];
    int gi = blockIdx.x;
    int t = threadIdx.x;  // 64 threads
    float inv = 1.0f / fmaxf(g_cnt[gi], 1.0f);
    gm[t]      = g_pool[(size_t)gi * 128 + t] * inv;
    gm[t + 64] = g_pool[(size_t)gi * 128 + t + 64] * inv;
    __syncthreads();
    float s = bl1[t];
    #pragma unroll 8
    for (int k = 0; k < 128; k++) s += gm[k] * Wl1[k * 64 + t];
    hid[t] = fmaxf(s, 0.0f);
    __syncthreads();
    if (t < 5) {
        float o = bl2[t];
        #pragma unroll
        for (int k = 0; k < 64; k++) o += hid[k] * Wl2[k * 5 + t];
        out[gi * 5 + t] = 1.0f / (1.0f + expf(-o));
    }
}

// ---------------------------------------------------------------------------
extern "C" void kernel_launch(void* const* d_in, const int* in_sizes, int n_in,
                              void* d_out, int out_size) {
    const float* x    = (const float*)d_in[0];
    const int*   ei   = (const int*)d_in[1];   // [2, E] int32
    const int*   batch= (const int*)d_in[2];
    const float* W1   = (const float*)d_in[3];
    const float* b1   = (const float*)d_in[4];
    const float* W2   = (const float*)d_in[5];
    const float* b2   = (const float*)d_in[6];
    const float* Wl1  = (const float*)d_in[7];
    const float* bl1  = (const float*)d_in[8];
    const float* Wl2  = (const float*)d_in[9];
    const float* bl2  = (const float*)d_in[10];
    float* out = (float*)d_out;

    const int N = in_sizes[2];          // 50000
    const int E = in_sizes[1] / 2;      // 1600000
    const int* src = ei;
    const int* dst = ei + E;

    float* H = nullptr; float* B = nullptr;
    cudaGetSymbolAddress((void**)&H, g_H);
    cudaGetSymbolAddress((void**)&B, g_B);

    const int T = 256;
    const int nb_scan = (N + 1 + 255) / 256;   // scan covers indices 0..N

    // CSR build + dis
    k_zero_deg<<<(N + T - 1) / T, T>>>(N);
    k_edge_count<<<(E + T - 1) / T, T>>>(dst, E);
    k_dis<<<(N + T - 1) / T, T>>>(N);
    k_block_sums<<<nb_scan, 256>>>(N);
    k_scan_partials<<<1, 256>>>(nb_scan);
    k_scan_final<<<nb_scan, 256>>>(N);
    k_fill_csr<<<(E + T - 1) / T, T>>>(src, dst, E);

    // layer 1: gemm(x,W1) -> H ; aggregate(H) -> B (relu'd)
    k_gemm<IN_DIM><<<(N + 127) / 128, 256>>>(x, W1, H, N);
    k_aggregate<<<(N * 32 + T - 1) / T, T>>>(H, b1, B, N);

    // layer 2: gemm(B,W2) -> H ; aggregate(H) -> B
    k_gemm<HID><<<(N + 127) / 128, 256>>>(B, W2, H, N);
    k_aggregate<<<(N * 32 + T - 1) / T, T>>>(H, b2, B, N);

    // pooling + head
    k_pool_zero<<<(N_GRAPHS * HID + T - 1) / T, T>>>();
    k_pool<<<(N * 32 + T - 1) / T, T>>>(B, batch, N);
    k_mlp<<<N_GRAPHS, 64>>>(Wl1, bl1, Wl2, bl2, out);
}

// round 3
// speedup vs baseline: 1.6455x; 1.0003x over previous
#include <cuda_runtime.h>
#include <cuda_bf16.h>
#include <math.h>

// ---------------------------------------------------------------------------
// GNNRegressor: 2x GCNConv(+relu) -> global_mean_pool -> Linear+relu -> Linear+sigmoid
// N=50000 nodes, E=1.6M edges, IN=384, HID=128, G=512, OUT=5
// Strategy: per-call CSR build (by dst), register-accumulating aggregate
// (1 warp/node), 128x128 SIMT fp32 GEMM.
// ---------------------------------------------------------------------------

#define N_NODES 50000
#define N_GRAPHS 512
#define HID 128
#define IN_DIM 384
#define E_MAX 1600000

// Scratch (device globals; no allocation allowed)
__device__ float g_H[(size_t)N_NODES * HID];     // gemm output (pre-aggregate)
__device__ float g_B[(size_t)N_NODES * HID];     // aggregate output (post-relu)
__device__ float g_dis[N_NODES];                 // rsqrt(deg+1)
__device__ int   g_deg[N_NODES];
__device__ int   g_row[N_NODES + 1];
__device__ int   g_cursor[N_NODES];
__device__ int   g_csr[E_MAX];
__device__ int   g_partials[256];
__device__ float g_pool[(size_t)N_GRAPHS * HID];
__device__ float g_cnt[N_GRAPHS];

__device__ __forceinline__ void red_add_v4(float* addr, float4 v) {
    asm volatile("red.global.add.v4.f32 [%0], {%1,%2,%3,%4};"
                 :: "l"(addr), "f"(v.x), "f"(v.y), "f"(v.z), "f"(v.w)
                 : "memory");
}

// ---- degree + CSR build -----------------------------------------------------
__global__ void k_zero_deg(int n) {
    int i = blockIdx.x * blockDim.x + threadIdx.x;
    if (i < n) g_deg[i] = 0;
}

__global__ void k_edge_count(const int* __restrict__ dst, int E) {
    int e = blockIdx.x * blockDim.x + threadIdx.x;
    if (e < E) atomicAdd(&g_deg[dst[e]], 1);
}

__global__ void k_dis(int n) {
    int i = blockIdx.x * blockDim.x + threadIdx.x;
    if (i < n) g_dis[i] = rsqrtf((float)(g_deg[i] + 1));
}

// block sums over 256-elem chunks of deg (covers n+1 with deg[n]=0 virtual)
__global__ void k_block_sums(int n) {
    __shared__ int sh[256];
    int i = blockIdx.x * 256 + threadIdx.x;
    int v = (i < n) ? g_deg[i] : 0;
    sh[threadIdx.x] = v;
    __syncthreads();
    #pragma unroll
    for (int off = 128; off > 0; off >>= 1) {
        if (threadIdx.x < off) sh[threadIdx.x] += sh[threadIdx.x + off];
        __syncthreads();
    }
    if (threadIdx.x == 0) g_partials[blockIdx.x] = sh[0];
}

// exclusive scan of partials (<=256) in one block
__global__ void k_scan_partials(int nb) {
    __shared__ int sh[256];
    int t = threadIdx.x;
    int v = (t < nb) ? g_partials[t] : 0;
    sh[t] = v;
    __syncthreads();
    #pragma unroll
    for (int off = 1; off < 256; off <<= 1) {
        int x = (t >= off) ? sh[t - off] : 0;
        __syncthreads();
        sh[t] += x;
        __syncthreads();
    }
    if (t < nb) g_partials[t] = sh[t] - v;  // exclusive
}

// final scan: row_start[i] = exclusive prefix of deg; also copy to cursor
__global__ void k_scan_final(int n) {
    __shared__ int sh[256];
    int i = blockIdx.x * 256 + threadIdx.x;
    int t = threadIdx.x;
    int v = (i < n) ? g_deg[i] : 0;
    sh[t] = v;
    __syncthreads();
    #pragma unroll
    for (int off = 1; off < 256; off <<= 1) {
        int x = (t >= off) ? sh[t - off] : 0;
        __syncthreads();
        sh[t] += x;
        __syncthreads();
    }
    int excl = sh[t] - v + g_partials[blockIdx.x];
    if (i <= n) {
        g_row[i] = excl;
        if (i < n) g_cursor[i] = excl;
    }
}

__global__ void k_fill_csr(const int* __restrict__ src, const int* __restrict__ dst, int E) {
    int e = blockIdx.x * blockDim.x + threadIdx.x;
    if (e < E) {
        int d = dst[e];
        int pos = atomicAdd(&g_cursor[d], 1);
        g_csr[pos] = src[e];
    }
}

// ---- GEMM: C[M,128] = A[M,K] @ W[K,128], fp32 SIMT, 128x128 tile -----------
template <int KTOT>
__global__ __launch_bounds__(256, 2)
void k_gemm(const float* __restrict__ A, const float* __restrict__ W,
            float* __restrict__ C, int M) {
    constexpr int BM = 128, BN = 128, BK = 8;
    __shared__ float As[BK][BM];
    __shared__ float Bs[BK][BN];
    const int t = threadIdx.x;                 // 256 threads
    const int rg = t >> 4;                     // 0..15
    const int cg = t & 15;                     // 0..15
    const int row0 = blockIdx.x * BM;

    const int arow = t >> 1;                   // 0..127
    const int acol = (t & 1) * 4;              // 0 or 4
    const int brow = t >> 5;                   // 0..7
    const int bcol = (t & 31) * 4;             // 0..124

    float acc00[4][4] = {}, acc01[4][4] = {}, acc10[4][4] = {}, acc11[4][4] = {};

    for (int k0 = 0; k0 < KTOT; k0 += BK) {
        int grow = row0 + arow;
        float4 av = (grow < M) ? *(const float4*)&A[(size_t)grow * KTOT + k0 + acol]
                               : make_float4(0.f, 0.f, 0.f, 0.f);
        As[acol + 0][arow] = av.x;
        As[acol + 1][arow] = av.y;
        As[acol + 2][arow] = av.z;
        As[acol + 3][arow] = av.w;
        *(float4*)&Bs[brow][bcol] = *(const float4*)&W[(size_t)(k0 + brow) * BN + bcol];
        __syncthreads();

        #pragma unroll
        for (int kk = 0; kk < BK; kk++) {
            float4 a0 = *(float4*)&As[kk][rg * 4];
            float4 a1 = *(float4*)&As[kk][rg * 4 + 64];
            float4 b0 = *(float4*)&Bs[kk][cg * 4];
            float4 b1 = *(float4*)&Bs[kk][cg * 4 + 64];
            float a0v[4] = {a0.x, a0.y, a0.z, a0.w};
            float a1v[4] = {a1.x, a1.y, a1.z, a1.w};
            float b0v[4] = {b0.x, b0.y, b0.z, b0.w};
            float b1v[4] = {b1.x, b1.y, b1.z, b1.w};
            #pragma unroll
            for (int i = 0; i < 4; i++)
                #pragma unroll
                for (int j = 0; j < 4; j++) {
                    acc00[i][j] += a0v[i] * b0v[j];
                    acc01[i][j] += a0v[i] * b1v[j];
                    acc10[i][j] += a1v[i] * b0v[j];
                    acc11[i][j] += a1v[i] * b1v[j];
                }
        }
        __syncthreads();
    }

    #pragma unroll
    for (int i = 0; i < 4; i++) {
        int r0 = row0 + rg * 4 + i;
        int r1 = r0 + 64;
        if (r0 < M) {
            *(float4*)&C[(size_t)r0 * 128 + cg * 4]      = *(float4*)&acc00[i][0];
            *(float4*)&C[(size_t)r0 * 128 + cg * 4 + 64] = *(float4*)&acc01[i][0];
        }
        if (r1 < M) {
            *(float4*)&C[(size_t)r1 * 128 + cg * 4]      = *(float4*)&acc10[i][0];
            *(float4*)&C[(size_t)r1 * 128 + cg * 4 + 64] = *(float4*)&acc11[i][0];
        }
    }
}

// ---- aggregate: out[d] = relu(dis_d*(Sum_{s in row d} dis_s*h[s] + dis_d*h[d]) + bias)
__global__ void k_aggregate(const float* __restrict__ H, const float* __restrict__ bias,
                            float* __restrict__ out, int n) {
    int warp = (blockIdx.x * blockDim.x + threadIdx.x) >> 5;
    int lane = threadIdx.x & 31;
    if (warp >= n) return;
    const int node = warp;
    const float4* __restrict__ H4 = (const float4*)H;

    int beg = g_row[node];
    int end = g_row[node + 1];

    float4 a0 = {0, 0, 0, 0}, a1 = {0, 0, 0, 0}, a2 = {0, 0, 0, 0}, a3 = {0, 0, 0, 0};

    int j = beg;
    for (; j + 3 < end; j += 4) {
        int s0 = __ldg(&g_csr[j + 0]);
        int s1 = __ldg(&g_csr[j + 1]);
        int s2 = __ldg(&g_csr[j + 2]);
        int s3 = __ldg(&g_csr[j + 3]);
        float w0 = __ldg(&g_dis[s0]);
        float w1 = __ldg(&g_dis[s1]);
        float w2 = __ldg(&g_dis[s2]);
        float w3 = __ldg(&g_dis[s3]);
        float4 h0 = __ldg(&H4[(size_t)s0 * 32 + lane]);
        float4 h1 = __ldg(&H4[(size_t)s1 * 32 + lane]);
        float4 h2 = __ldg(&H4[(size_t)s2 * 32 + lane]);
        float4 h3 = __ldg(&H4[(size_t)s3 * 32 + lane]);
        a0.x += w0 * h0.x; a0.y += w0 * h0.y; a0.z += w0 * h0.z; a0.w += w0 * h0.w;
        a1.x += w1 * h1.x; a1.y += w1 * h1.y; a1.z += w1 * h1.z; a1.w += w1 * h1.w;
        a2.x += w2 * h2.x; a2.y += w2 * h2.y; a2.z += w2 * h2.z; a2.w += w2 * h2.w;
        a3.x += w3 * h3.x; a3.y += w3 * h3.y; a3.z += w3 * h3.z; a3.w += w3 * h3.w;
    }
    for (; j < end; j++) {
        int s = __ldg(&g_csr[j]);
        float w = __ldg(&g_dis[s]);
        float4 h = __ldg(&H4[(size_t)s * 32 + lane]);
        a0.x += w * h.x; a0.y += w * h.y; a0.z += w * h.z; a0.w += w * h.w;
    }

    float dd = g_dis[node];
    float4 hs = __ldg(&H4[(size_t)node * 32 + lane]);
    float4 acc;
    acc.x = dd * ((a0.x + a1.x) + (a2.x + a3.x) + dd * hs.x);
    acc.y = dd * ((a0.y + a1.y) + (a2.y + a3.y) + dd * hs.y);
    acc.z = dd * ((a0.z + a1.z) + (a2.z + a3.z) + dd * hs.z);
    acc.w = dd * ((a0.w + a1.w) + (a2.w + a3.w) + dd * hs.w);

    float4 b = *(const float4*)&bias[lane * 4];
    acc.x = fmaxf(acc.x + b.x, 0.f);
    acc.y = fmaxf(acc.y + b.y, 0.f);
    acc.z = fmaxf(acc.z + b.z, 0.f);
    acc.w = fmaxf(acc.w + b.w, 0.f);
    ((float4*)out)[(size_t)node * 32 + lane] = acc;
}

// ---- pooling ---------------------------------------------------------------
__global__ void k_pool_zero() {
    int i = blockIdx.x * blockDim.x + threadIdx.x;
    if (i < N_GRAPHS * HID) g_pool[i] = 0.0f;
    if (i < N_GRAPHS) g_cnt[i] = 0.0f;
}

__global__ void k_pool(const float* __restrict__ H, const int* __restrict__ batch, int n) {
    int idx = blockIdx.x * blockDim.x + threadIdx.x;
    int node = idx >> 5, chunk = idx & 31;
    if (node >= n) return;
    int b = __ldg(&batch[node]);
    float4 h = ((const float4*)(H + (size_t)node * 128))[chunk];
    red_add_v4(&g_pool[(size_t)b * 128 + chunk * 4], h);
    if (chunk == 0) atomicAdd(&g_cnt[b], 1.0f);
}

// ---- MLP head: [512,128] -> relu(@Wl1[128,64]+bl1) -> sigmoid(@Wl2[64,5]+bl2)
__global__ void k_mlp(const float* __restrict__ Wl1, const float* __restrict__ bl1,
                      const float* __restrict__ Wl2, const float* __restrict__ bl2,
                      float* __restrict__ out) {
    __shared__ float gm[128];
    __shared__ float hid[64];
    int gi = blockIdx.x;
    int t = threadIdx.x;  // 64 threads
    float inv = 1.0f / fmaxf(g_cnt[gi], 1.0f);
    gm[t]      = g_pool[(size_t)gi * 128 + t] * inv;
    gm[t + 64] = g_pool[(size_t)gi * 128 + t + 64] * inv;
    __syncthreads();
    float s = bl1[t];
    #pragma unroll 8
    for (int k = 0; k < 128; k++) s += gm[k] * Wl1[k * 64 + t];
    hid[t] = fmaxf(s, 0.0f);
    __syncthreads();
    if (t < 5) {
        float o = bl2[t];
        #pragma unroll
        for (int k = 0; k < 64; k++) o += hid[k] * Wl2[k * 5 + t];
        out[gi * 5 + t] = 1.0f / (1.0f + expf(-o));
    }
}

// ---------------------------------------------------------------------------
extern "C" void kernel_launch(void* const* d_in, const int* in_sizes, int n_in,
                              void* d_out, int out_size) {
    const float* x    = (const float*)d_in[0];
    const int*   ei   = (const int*)d_in[1];   // [2, E] int32
    const int*   batch= (const int*)d_in[2];
    const float* W1   = (const float*)d_in[3];
    const float* b1   = (const float*)d_in[4];
    const float* W2   = (const float*)d_in[5];
    const float* b2   = (const float*)d_in[6];
    const float* Wl1  = (const float*)d_in[7];
    const float* bl1  = (const float*)d_in[8];
    const float* Wl2  = (const float*)d_in[9];
    const float* bl2  = (const float*)d_in[10];
    float* out = (float*)d_out;

    const int N = in_sizes[2];          // 50000
    const int E = in_sizes[1] / 2;      // 1600000
    const int* src = ei;
    const int* dst = ei + E;

    float* H = nullptr; float* B = nullptr;
    cudaGetSymbolAddress((void**)&H, g_H);
    cudaGetSymbolAddress((void**)&B, g_B);

    const int T = 256;
    const int nb_scan = (N + 1 + 255) / 256;   // scan covers indices 0..N

    // CSR build + dis
    k_zero_deg<<<(N + T - 1) / T, T>>>(N);
    k_edge_count<<<(E + T - 1) / T, T>>>(dst, E);
    k_dis<<<(N + T - 1) / T, T>>>(N);
    k_block_sums<<<nb_scan, 256>>>(N);
    k_scan_partials<<<1, 256>>>(nb_scan);
    k_scan_final<<<nb_scan, 256>>>(N);
    k_fill_csr<<<(E + T - 1) / T, T>>>(src, dst, E);

    // layer 1: gemm(x,W1) -> H ; aggregate(H) -> B (relu'd)
    k_gemm<IN_DIM><<<(N + 127) / 128, 256>>>(x, W1, H, N);
    k_aggregate<<<(N * 32 + T - 1) / T, T>>>(H, b1, B, N);

    // layer 2: gemm(B,W2) -> H ; aggregate(H) -> B
    k_gemm<HID><<<(N + 127) / 128, 256>>>(B, W2, H, N);
    k_aggregate<<<(N * 32 + T - 1) / T, T>>>(H, b2, B, N);

    // pooling + head
    k_pool_zero<<<(N_GRAPHS * HID + T - 1) / T, T>>>();
    k_pool<<<(N * 32 + T - 1) / T, T>>>(B, batch, N);
    k_mlp<<<N_GRAPHS, 64>>>(Wl1, bl1, Wl2, bl2, out);
}